// round 10
// baseline (speedup 1.0000x reference)
#include <cuda_runtime.h>
#include <cuda_fp16.h>
#include <mma.h>
#include <math.h>

using namespace nvcuda;

// Problem constants (fixed shapes)
#define NN 4096
#define DD 256
#define NW 128          // adjacency words per row (4096/32)
#define MAXD 512        // max neighbors kept (avg ~64 for random E=131072 graph)

// -------- static device scratch --------
__device__ unsigned g_adj[NN * NW];        // 2 MB bitmask adjacency
__device__ int      g_deg[NN];
__device__ int      g_nbr[NN * MAXD];      // 8 MB compact neighbor lists (sorted)
__device__ float    g_q  [NN * DD];        // 4 MB  (q, fp32)
__device__ uint4    g_kvh_raw[NN * 64];    // 4 MB  (k,v as fp16: 512 halves/node)
__device__ float    g_ctx[NN * DD];        // 4 MB
__device__ float    g_y  [NN * DD];        // 4 MB
__device__ float    g_wc [DD * DD];        // 256 KB  combined weight Wc = Wlin @ Wout
__device__ float    g_bc [DD];             //         combined bias  bc = Wlin·bout + blin

// -------- scatter edges (symmetric, no self loops, dedup via OR); edge_index is int32 --------
__global__ void build_adj_kernel(const int* __restrict__ ei, int ne) {
    int e = blockIdx.x * blockDim.x + threadIdx.x;
    if (e >= ne) return;
    int s = ei[e];
    int d = ei[ne + e];
    if (s == d) return;
    if ((unsigned)s >= NN || (unsigned)d >= NN) return;
    atomicOr(&g_adj[s * NW + (d >> 5)], 1u << (d & 31));
    atomicOr(&g_adj[d * NW + (s >> 5)], 1u << (s & 31));
}

// -------- deterministic compaction (also re-zeroes g_adj for next graph replay) --------
__global__ void compact_kernel() {
    __shared__ int wsum[4];
    int n = blockIdx.x, t = threadIdx.x;
    unsigned bits = g_adj[n * NW + t];
    g_adj[n * NW + t] = 0u;                 // reset for next replay (row-exclusive)
    int c = __popc(bits);
    int lane = t & 31, w = t >> 5;
    int x = c;
#pragma unroll
    for (int o = 1; o < 32; o <<= 1) {
        int y = __shfl_up_sync(0xffffffffu, x, o);
        if (lane >= o) x += y;
    }
    if (lane == 31) wsum[w] = x;
    __syncthreads();
    int woff = 0;
#pragma unroll
    for (int i = 0; i < 4; i++) if (i < w) woff += wsum[i];
    int base = woff + x - c;                // exclusive prefix
    int total = wsum[0] + wsum[1] + wsum[2] + wsum[3];
    while (bits) {
        int b = __ffs(bits) - 1;
        bits &= bits - 1;
        if (base < MAXD) g_nbr[n * MAXD + base] = t * 32 + b;
        base++;
    }
    if (t == 0) g_deg[n] = (total < MAXD) ? total : MAXD;
}

// -------- Wc = Wlin @ Wout (fp32 SIMT, 256x256x256; 16 blocks) --------
// Wc[i][k] = sum_m Wlin[i][m] * Wout[m][k]
__global__ __launch_bounds__(256) void combine_w_kernel(const float* __restrict__ wlin,
                                                        const float* __restrict__ wout) {
    __shared__ float As[16][68];   // As[m][i]
    __shared__ float Bs[16][68];   // Bs[m][k]
    int tid = threadIdx.x;
    int i0 = blockIdx.y * 64, k0 = blockIdx.x * 64;
    int tx = tid & 15, ty = tid >> 4;
    float acc[4][4] = {};

    for (int m0 = 0; m0 < DD; m0 += 16) {
        // As: 64 i-rows x 16 m (m-contig in Wlin)
        {
            int i = tid >> 2, mc = (tid & 3) * 4;
            float4 v = *(const float4*)(wlin + (size_t)(i0 + i) * DD + m0 + mc);
            As[mc + 0][i] = v.x; As[mc + 1][i] = v.y;
            As[mc + 2][i] = v.z; As[mc + 3][i] = v.w;
        }
        // Bs: 16 m-rows x 64 k (k-contig in Wout)
        {
            int m = tid >> 4, kc = (tid & 15) * 4;
            float4 v = *(const float4*)(wout + (size_t)(m0 + m) * DD + k0 + kc);
            *(float4*)&Bs[m][kc] = v;
        }
        __syncthreads();
#pragma unroll
        for (int m = 0; m < 16; m++) {
            float a[4], b[4];
#pragma unroll
            for (int u = 0; u < 4; u++) a[u] = As[m][ty * 4 + u];
#pragma unroll
            for (int u = 0; u < 4; u++) b[u] = Bs[m][tx * 4 + u];
#pragma unroll
            for (int u = 0; u < 4; u++)
#pragma unroll
                for (int v = 0; v < 4; v++)
                    acc[u][v] += a[u] * b[v];
        }
        __syncthreads();
    }
#pragma unroll
    for (int u = 0; u < 4; u++)
#pragma unroll
        for (int v = 0; v < 4; v++)
            g_wc[(size_t)(i0 + ty * 4 + u) * DD + k0 + tx * 4 + v] = acc[u][v];
}

// -------- bc = Wlin @ bout + blin (1 block) --------
__global__ __launch_bounds__(256) void combine_b_kernel(const float* __restrict__ wlin,
                                                        const float* __restrict__ bout,
                                                        const float* __restrict__ blin) {
    __shared__ float sb[DD];
    int t = threadIdx.x;
    sb[t] = bout[t];
    __syncthreads();
    float acc = blin[t];
    const float* row = wlin + (size_t)t * DD;
#pragma unroll 8
    for (int k = 0; k < DD; k += 4) {
        float4 v = *(const float4*)(row + k);
        acc += v.x * sb[k] + v.y * sb[k + 1] + v.z * sb[k + 2] + v.w * sb[k + 3];
    }
    g_bc[t] = acc;
}

// ======== tf32 wmma GEMM: C[M,Nc] = A[M,K] @ B[Nc,K]^T + bias ========
// BM=64, BN=64, BK=16, 128 threads (4 warps 2x2, warp tile 32x32 = 2x2 m16n16k8),
// double-buffered smem, tf32 RN at smem store, smem-staged epilogue.
// ASEL: 0 = emb, 1 = g_ctx
// CSEL: 0 = qkv split output (q fp32 / kv fp16), 2 = g_y with B=g_wc, bias=g_bc
#define BM 64
#define BN 64
#define GBK 16
#define BKP 20
#define GNT 128

struct GemmSmem {
    union {
        struct {
            float As[2][BM][BKP];   // 10240 B
            float Bs[2][BN][BKP];   // 10240 B
        } p;
        float stage[4][32][36];     // 18432 B (epilogue staging)
    };
};

template<int ASEL, int CSEL>
__global__ __launch_bounds__(GNT) void gemm_kernel(const float* __restrict__ emb,
                                                   const float* __restrict__ Barg,
                                                   const float* __restrict__ biasarg,
                                                   int Nc) {
    const float* A = (ASEL == 0) ? emb : (const float*)g_ctx;
    const float* B = (CSEL == 2) ? (const float*)g_wc : Barg;
    const float* bias = (CSEL == 2) ? (const float*)g_bc : biasarg;
    const int K = DD;

    __shared__ GemmSmem sm;

    const int tid = threadIdx.x;
    const int w = tid >> 5, lane = tid & 31;
    const int wy = w >> 1, wx = w & 1;          // warp grid 2x2
    const int row0 = blockIdx.y * BM;
    const int col0 = blockIdx.x * BN;

    float4 ra[2], rb[2];
    auto gload = [&](int k0) {
#pragma unroll
        for (int u = 0; u < 2; u++) {
            int i = tid + u * GNT;
            int r = i >> 2, kk = (i & 3) * 4;
            ra[u] = *(const float4*)(A + (size_t)(row0 + r) * K + k0 + kk);
            rb[u] = *(const float4*)(B + (size_t)(col0 + r) * K + k0 + kk);
        }
    };
    auto sstore = [&](int buf) {
#pragma unroll
        for (int u = 0; u < 2; u++) {
            int i = tid + u * GNT;
            int r = i >> 2, kk = (i & 3) * 4;
            sm.p.As[buf][r][kk + 0] = wmma::__float_to_tf32(ra[u].x);
            sm.p.As[buf][r][kk + 1] = wmma::__float_to_tf32(ra[u].y);
            sm.p.As[buf][r][kk + 2] = wmma::__float_to_tf32(ra[u].z);
            sm.p.As[buf][r][kk + 3] = wmma::__float_to_tf32(ra[u].w);
            sm.p.Bs[buf][r][kk + 0] = wmma::__float_to_tf32(rb[u].x);
            sm.p.Bs[buf][r][kk + 1] = wmma::__float_to_tf32(rb[u].y);
            sm.p.Bs[buf][r][kk + 2] = wmma::__float_to_tf32(rb[u].z);
            sm.p.Bs[buf][r][kk + 3] = wmma::__float_to_tf32(rb[u].w);
        }
    };

    wmma::fragment<wmma::accumulator, 16, 16, 8, float> cf[2][2];
#pragma unroll
    for (int i = 0; i < 2; i++)
#pragma unroll
        for (int j = 0; j < 2; j++)
            wmma::fill_fragment(cf[i][j], 0.0f);

    gload(0);
    sstore(0);
    __syncthreads();

    const int KT = K / GBK;
    for (int kt = 0; kt < KT; kt++) {
        int buf = kt & 1;
        if (kt + 1 < KT) gload((kt + 1) * GBK);
#pragma unroll
        for (int ks = 0; ks < GBK; ks += 8) {
            wmma::fragment<wmma::matrix_a, 16, 16, 8, wmma::precision::tf32, wmma::row_major> af[2];
            wmma::fragment<wmma::matrix_b, 16, 16, 8, wmma::precision::tf32, wmma::col_major> bf[2];
#pragma unroll
            for (int i = 0; i < 2; i++)
                wmma::load_matrix_sync(af[i], &sm.p.As[buf][wy * 32 + i * 16][ks], BKP);
#pragma unroll
            for (int j = 0; j < 2; j++)
                wmma::load_matrix_sync(bf[j], &sm.p.Bs[buf][wx * 32 + j * 16][ks], BKP);
#pragma unroll
            for (int i = 0; i < 2; i++)
#pragma unroll
                for (int j = 0; j < 2; j++)
                    wmma::mma_sync(cf[i][j], af[i], bf[j], cf[i][j]);
        }
        if (kt + 1 < KT) {
            sstore(buf ^ 1);
            __syncthreads();
        }
    }

    // epilogue: stage accumulators to smem, add bias, route to destination
    __syncthreads();
#pragma unroll
    for (int i = 0; i < 2; i++)
#pragma unroll
        for (int j = 0; j < 2; j++)
            wmma::store_matrix_sync(&sm.stage[w][i * 16][j * 16], cf[i][j], 36, wmma::mem_row_major);
    __syncwarp();

    {
        int r = row0 + wy * 32 + lane;
        int cbase = col0 + wx * 32;
#pragma unroll
        for (int j = 0; j < 8; j++) {
            int cc = cbase + j * 4;
            float4 bv = *(const float4*)(bias + cc);
            float4 v;
            v.x = sm.stage[w][lane][j * 4 + 0] + bv.x;
            v.y = sm.stage[w][lane][j * 4 + 1] + bv.y;
            v.z = sm.stage[w][lane][j * 4 + 2] + bv.z;
            v.w = sm.stage[w][lane][j * 4 + 3] + bv.w;
            if (CSEL == 0) {
                if (cbase < 256) {                       // q -> fp32
                    *(float4*)(g_q + (size_t)r * DD + cc) = v;
                } else {                                 // k,v -> fp16
                    __half2 h01 = __floats2half2_rn(v.x, v.y);
                    __half2 h23 = __floats2half2_rn(v.z, v.w);
                    uint2 hv;
                    hv.x = *(unsigned*)&h01;
                    hv.y = *(unsigned*)&h23;
                    *(uint2*)((__half*)g_kvh_raw + (size_t)r * 512 + (cc - 256)) = hv;
                }
            } else {
                *(float4*)(g_y + (size_t)r * Nc + cc) = v;
            }
        }
    }
}

// -------- fixup: rows with deg==0 take y = emb @ Wlin^T + blin (fp32, rare path) --------
__global__ __launch_bounds__(256) void fixup_kernel(const float* __restrict__ emb,
                                                    const float* __restrict__ wlin,
                                                    const float* __restrict__ blin) {
    int n = blockIdx.x;
    if (g_deg[n] != 0) return;
    __shared__ float se[DD];
    int t = threadIdx.x;
    se[t] = emb[(size_t)n * DD + t];
    __syncthreads();
    float acc = blin[t];
    const float* row = wlin + (size_t)t * DD;
#pragma unroll 8
    for (int k = 0; k < DD; k += 4) {
        float4 v = *(const float4*)(row + k);
        acc += v.x * se[k] + v.y * se[k + 1] + v.z * se[k + 2] + v.w * se[k + 3];
    }
    g_y[(size_t)n * DD + t] = acc;
}

// ======== sparse attention (fp16 k/v): 4-lane dot groups, 16 neighbors per warp-iter ========
__global__ __launch_bounds__(256) void attn_kernel() {
    __shared__ int snbr[MAXD];
    __shared__ int sdeg;
    int n = blockIdx.x, tid = threadIdx.x;
    int w = tid >> 5, lane = tid & 31;
    int g = lane >> 2, d8 = (lane & 3) * 8;
    if (tid == 0) sdeg = g_deg[n];
    __syncthreads();
    int dg = sdeg;
    for (int i = tid; i < dg; i += 256)
        snbr[i] = g_nbr[(size_t)n * MAXD + i] * 512;   // pre-scaled element offset
    __syncthreads();

    const int woff = w * 32 + d8;

    if (dg == 0) {
        if (lane < 4) {
            *(float4*)&g_ctx[(size_t)n * DD + woff]     = make_float4(0.f, 0.f, 0.f, 0.f);
            *(float4*)&g_ctx[(size_t)n * DD + woff + 4] = make_float4(0.f, 0.f, 0.f, 0.f);
        }
        return;
    }

    float q8[8];
    *(float4*)&q8[0] = *(const float4*)(g_q + (size_t)n * DD + woff);
    *(float4*)&q8[4] = *(const float4*)(g_q + (size_t)n * DD + woff + 4);

    const float sc = 0.17677669529663687f;    // 1/sqrt(32)
    float s = 0.f;
    float acc[8] = {};
    const __half* kvh = (const __half*)g_kvh_raw;

    for (int i = 0; i < dg; i += 16) {
        int idx0 = i + g, idx1 = i + 8 + g;
        bool va = idx0 < dg, vb = idx1 < dg;
        const __half* pa = kvh + snbr[va ? idx0 : i] + woff;
        const __half* pb = kvh + snbr[vb ? idx1 : i] + woff;
        uint4 ka = *(const uint4*)pa;
        uint4 kb = *(const uint4*)pb;
        uint4 vaa = *(const uint4*)(pa + 256);
        uint4 vbb = *(const uint4*)(pb + 256);

        float2 a0 = __half22float2(*(__half2*)&ka.x);
        float2 a1 = __half22float2(*(__half2*)&ka.y);
        float2 a2 = __half22float2(*(__half2*)&ka.z);
        float2 a3 = __half22float2(*(__half2*)&ka.w);
        float2 b0 = __half22float2(*(__half2*)&kb.x);
        float2 b1 = __half22float2(*(__half2*)&kb.y);
        float2 b2 = __half22float2(*(__half2*)&kb.z);
        float2 b3 = __half22float2(*(__half2*)&kb.w);

        float p0 = q8[0] * a0.x + q8[1] * a0.y + q8[2] * a1.x + q8[3] * a1.y
                 + q8[4] * a2.x + q8[5] * a2.y + q8[6] * a3.x + q8[7] * a3.y;
        float p1 = q8[0] * b0.x + q8[1] * b0.y + q8[2] * b1.x + q8[3] * b1.y
                 + q8[4] * b2.x + q8[5] * b2.y + q8[6] * b3.x + q8[7] * b3.y;
        p0 += __shfl_xor_sync(0xffffffffu, p0, 1);
        p1 += __shfl_xor_sync(0xffffffffu, p1, 1);
        p0 += __shfl_xor_sync(0xffffffffu, p0, 2);
        p1 += __shfl_xor_sync(0xffffffffu, p1, 2);
        p0 = va ? fminf(p0 * sc, 80.f) : -INFINITY;
        p1 = vb ? fminf(p1 * sc, 80.f) : -INFINITY;
        float e0 = __expf(p0);
        float e1 = __expf(p1);
        s += e0 + e1;

        float2 w0 = __half22float2(*(__half2*)&vaa.x);
        float2 w1 = __half22float2(*(__half2*)&vaa.y);
        float2 w2 = __half22float2(*(__half2*)&vaa.z);
        float2 w3 = __half22float2(*(__half2*)&vaa.w);
        acc[0] += e0 * w0.x; acc[1] += e0 * w0.y;
        acc[2] += e0 * w1.x; acc[3] += e0 * w1.y;
        acc[4] += e0 * w2.x; acc[5] += e0 * w2.y;
        acc[6] += e0 * w3.x; acc[7] += e0 * w3.y;
        float2 u0 = __half22float2(*(__half2*)&vbb.x);
        float2 u1 = __half22float2(*(__half2*)&vbb.y);
        float2 u2 = __half22float2(*(__half2*)&vbb.z);
        float2 u3 = __half22float2(*(__half2*)&vbb.w);
        acc[0] += e1 * u0.x; acc[1] += e1 * u0.y;
        acc[2] += e1 * u1.x; acc[3] += e1 * u1.y;
        acc[4] += e1 * u2.x; acc[5] += e1 * u2.y;
        acc[6] += e1 * u3.x; acc[7] += e1 * u3.y;
    }

    // merge the 8 group states (lanes differing in bits 2,3,4)
#pragma unroll
    for (int o = 4; o <= 16; o <<= 1) {
        s += __shfl_xor_sync(0xffffffffu, s, o);
#pragma unroll
        for (int j = 0; j < 8; j++)
            acc[j] += __shfl_xor_sync(0xffffffffu, acc[j], o);
    }
    if (lane < 4) {
        float inv = 1.f / s;
        float4 o0 = make_float4(acc[0] * inv, acc[1] * inv, acc[2] * inv, acc[3] * inv);
        float4 o1 = make_float4(acc[4] * inv, acc[5] * inv, acc[6] * inv, acc[7] * inv);
        *(float4*)&g_ctx[(size_t)n * DD + woff]     = o0;
        *(float4*)&g_ctx[(size_t)n * DD + woff + 4] = o1;
    }
}

// -------- fused LayerNorm + exact GELU --------
__global__ void ln_gelu_kernel(const float* __restrict__ g, const float* __restrict__ beta,
                               float* __restrict__ out) {
    __shared__ float red1[8];
    __shared__ float red2[8];
    int r = blockIdx.x;
    int t = threadIdx.x;
    float v = g_y[(size_t)r * DD + t];

    float x = v, x2 = v * v;
#pragma unroll
    for (int o = 16; o; o >>= 1) {
        x  += __shfl_xor_sync(0xffffffffu, x, o);
        x2 += __shfl_xor_sync(0xffffffffu, x2, o);
    }
    if ((t & 31) == 0) { red1[t >> 5] = x; red2[t >> 5] = x2; }
    __syncthreads();
    float sum = 0.f, ss = 0.f;
#pragma unroll
    for (int i = 0; i < 8; i++) { sum += red1[i]; ss += red2[i]; }
    float mean = sum * (1.f / 256.f);
    float var  = ss * (1.f / 256.f) - mean * mean;

    float yv = (v - mean) * rsqrtf(var + 1e-5f) * g[t] + beta[t];
    out[(size_t)r * DD + t] = 0.5f * yv * (1.f + erff(yv * 0.70710678118654752f));
}

// ------------------------------------------------------------------
extern "C" void kernel_launch(void* const* d_in, const int* in_sizes, int n_in,
                              void* d_out, int out_size) {
    const float* emb   = (const float*)d_in[0];
    const int*   ei    = (const int*)d_in[1];     // int32 (JAX default)
    const float* w_in  = (const float*)d_in[2];
    const float* b_in  = (const float*)d_in[3];
    const float* w_out = (const float*)d_in[4];
    const float* b_out = (const float*)d_in[5];
    const float* w_lin = (const float*)d_in[6];
    const float* b_lin = (const float*)d_in[7];
    const float* ln_g  = (const float*)d_in[8];
    const float* ln_b  = (const float*)d_in[9];
    float* out = (float*)d_out;

    const int ne = in_sizes[1] / 2;

    // 0. combined weight/bias (independent of everything else)
    combine_w_kernel<<<dim3(4, 4), 256>>>(w_lin, w_out);
    combine_b_kernel<<<1, 256>>>(w_lin, b_out, b_lin);

    // 1. adjacency (g_adj is zero at start; compact re-zeroes it for replay)
    build_adj_kernel<<<(ne + 255) / 256, 256>>>(ei, ne);
    compact_kernel<<<NN, NW>>>();

    // 2. qkv = emb @ W_in^T + b_in  -> q fp32 (g_q), k/v fp16 (g_kvh)
    gemm_kernel<0, 0><<<dim3(768 / BN, NN / BM), GNT>>>(emb, w_in, b_in, 768);

    // 3. sparse masked attention -> ctx [4096, 256]
    attn_kernel<<<NN, 256>>>();

    // 4. y = ctx @ Wc^T + bc   (fused out-proj + lin)
    gemm_kernel<1, 2><<<dim3(DD / BN, NN / BM), GNT>>>(emb, w_lin, b_lin, DD);

    // 5. rare deg==0 rows: y = emb @ Wlin^T + blin
    fixup_kernel<<<NN, 256>>>(emb, w_lin, b_lin);

    // 6. LayerNorm + exact GELU -> out
    ln_gelu_kernel<<<NN, 256>>>(ln_g, ln_b, out);
}

// round 11
// speedup vs baseline: 1.1518x; 1.1518x over previous
#include <cuda_runtime.h>
#include <cuda_fp16.h>
#include <mma.h>
#include <math.h>

using namespace nvcuda;

// Problem constants (fixed shapes)
#define NN 4096
#define DD 256
#define NW 128          // adjacency words per row (4096/32)
#define MAXD 512        // max neighbors kept (avg ~64 for random E=131072 graph)

// -------- static device scratch --------
__device__ unsigned g_adj[NN * NW];        // 2 MB bitmask adjacency
__device__ int      g_deg[NN];
__device__ int      g_nbr[NN * MAXD];      // 8 MB compact neighbor lists (pre-scaled *512)
__device__ float    g_q  [NN * DD];        // 4 MB  (q, fp32)
__device__ uint4    g_kvh_raw[NN * 64];    // 4 MB  (k,v as fp16: 512 halves/node)
__device__ float    g_ctx[NN * DD];        // 4 MB
__device__ float    g_x  [NN * DD];        // 4 MB
__device__ float    g_y  [NN * DD];        // 4 MB

// -------- scatter edges (symmetric, no self loops, dedup via OR); edge_index is int32 --------
__global__ void build_adj_kernel(const int* __restrict__ ei, int ne) {
    int e = blockIdx.x * blockDim.x + threadIdx.x;
    if (e >= ne) return;
    int s = ei[e];
    int d = ei[ne + e];
    if (s == d) return;
    if ((unsigned)s >= NN || (unsigned)d >= NN) return;
    atomicOr(&g_adj[s * NW + (d >> 5)], 1u << (d & 31));
    atomicOr(&g_adj[d * NW + (s >> 5)], 1u << (s & 31));
}

// -------- warp-per-row compaction (deterministic, sorted); re-zeroes g_adj for replay --------
// Block = 256 threads = 8 warps = 8 rows. Lane l owns words [4l, 4l+4) via one uint4.
__global__ __launch_bounds__(256) void compact_kernel() {
    int n = blockIdx.x * 8 + (threadIdx.x >> 5);
    int lane = threadIdx.x & 31;

    uint4 wv = *(uint4*)&g_adj[n * NW + lane * 4];
    *(uint4*)&g_adj[n * NW + lane * 4] = make_uint4(0u, 0u, 0u, 0u);  // reset for replay

    int c = __popc(wv.x) + __popc(wv.y) + __popc(wv.z) + __popc(wv.w);
    int x = c;
#pragma unroll
    for (int o = 1; o < 32; o <<= 1) {
        int y = __shfl_up_sync(0xffffffffu, x, o);
        if (lane >= o) x += y;
    }
    int total = __shfl_sync(0xffffffffu, x, 31);
    int base = x - c;                       // exclusive prefix

    int* dst = g_nbr + (size_t)n * MAXD;
    unsigned ws[4] = {wv.x, wv.y, wv.z, wv.w};
#pragma unroll
    for (int u = 0; u < 4; u++) {
        unsigned bits = ws[u];
        int boff = (lane * 4 + u) * 32;
        while (bits) {
            int b = __ffs(bits) - 1;
            bits &= bits - 1;
            if (base < MAXD) dst[base] = (boff + b) * 512;   // pre-scaled element offset
            base++;
        }
    }
    if (lane == 31) g_deg[n] = (total < MAXD) ? total : MAXD;
}

// ======== tf32 wmma GEMM: C[M,Nc] = A[M,K] @ B[Nc,K]^T + bias ========
// BM=64, BN=64, BK=16, 128 threads (4 warps 2x2, warp tile 32x32 = 2x2 m16n16k8),
// double-buffered smem, tf32 RN at smem store, smem-staged epilogue.
// ASEL: 0 = emb, 1 = g_ctx, 2 = g_x
// CSEL: 0 = qkv split output (q fp32 / kv fp16), 1 = g_x (+SELECT), 2 = g_y
#define BM 64
#define BN 64
#define GBK 16
#define BKP 20
#define GNT 128

struct GemmSmem {
    union {
        struct {
            float As[2][BM][BKP];   // 10240 B
            float Bs[2][BN][BKP];   // 10240 B
        } p;
        float stage[4][32][36];     // 18432 B (epilogue staging)
    };
};

template<int ASEL, int CSEL, bool SELECT>
__global__ __launch_bounds__(GNT) void gemm_kernel(const float* __restrict__ emb,
                                                   const float* __restrict__ B,
                                                   const float* __restrict__ bias,
                                                   int Nc) {
    const float* A = (ASEL == 0) ? emb : (ASEL == 1 ? (const float*)g_ctx : (const float*)g_x);
    const int K = DD;

    __shared__ GemmSmem sm;

    const int tid = threadIdx.x;
    const int w = tid >> 5, lane = tid & 31;
    const int wy = w >> 1, wx = w & 1;          // warp grid 2x2
    const int row0 = blockIdx.y * BM;
    const int col0 = blockIdx.x * BN;

    float4 ra[2], rb[2];
    auto gload = [&](int k0) {
#pragma unroll
        for (int u = 0; u < 2; u++) {
            int i = tid + u * GNT;
            int r = i >> 2, kk = (i & 3) * 4;
            ra[u] = *(const float4*)(A + (size_t)(row0 + r) * K + k0 + kk);
            rb[u] = *(const float4*)(B + (size_t)(col0 + r) * K + k0 + kk);
        }
    };
    auto sstore = [&](int buf) {
#pragma unroll
        for (int u = 0; u < 2; u++) {
            int i = tid + u * GNT;
            int r = i >> 2, kk = (i & 3) * 4;
            sm.p.As[buf][r][kk + 0] = wmma::__float_to_tf32(ra[u].x);
            sm.p.As[buf][r][kk + 1] = wmma::__float_to_tf32(ra[u].y);
            sm.p.As[buf][r][kk + 2] = wmma::__float_to_tf32(ra[u].z);
            sm.p.As[buf][r][kk + 3] = wmma::__float_to_tf32(ra[u].w);
            sm.p.Bs[buf][r][kk + 0] = wmma::__float_to_tf32(rb[u].x);
            sm.p.Bs[buf][r][kk + 1] = wmma::__float_to_tf32(rb[u].y);
            sm.p.Bs[buf][r][kk + 2] = wmma::__float_to_tf32(rb[u].z);
            sm.p.Bs[buf][r][kk + 3] = wmma::__float_to_tf32(rb[u].w);
        }
    };

    wmma::fragment<wmma::accumulator, 16, 16, 8, float> cf[2][2];
#pragma unroll
    for (int i = 0; i < 2; i++)
#pragma unroll
        for (int j = 0; j < 2; j++)
            wmma::fill_fragment(cf[i][j], 0.0f);

    gload(0);
    sstore(0);
    __syncthreads();

    const int KT = K / GBK;
    for (int kt = 0; kt < KT; kt++) {
        int buf = kt & 1;
        if (kt + 1 < KT) gload((kt + 1) * GBK);
#pragma unroll
        for (int ks = 0; ks < GBK; ks += 8) {
            wmma::fragment<wmma::matrix_a, 16, 16, 8, wmma::precision::tf32, wmma::row_major> af[2];
            wmma::fragment<wmma::matrix_b, 16, 16, 8, wmma::precision::tf32, wmma::col_major> bf[2];
#pragma unroll
            for (int i = 0; i < 2; i++)
                wmma::load_matrix_sync(af[i], &sm.p.As[buf][wy * 32 + i * 16][ks], BKP);
#pragma unroll
            for (int j = 0; j < 2; j++)
                wmma::load_matrix_sync(bf[j], &sm.p.Bs[buf][wx * 32 + j * 16][ks], BKP);
#pragma unroll
            for (int i = 0; i < 2; i++)
#pragma unroll
                for (int j = 0; j < 2; j++)
                    wmma::mma_sync(cf[i][j], af[i], bf[j], cf[i][j]);
        }
        if (kt + 1 < KT) {
            sstore(buf ^ 1);
            __syncthreads();
        }
    }

    // epilogue: stage accumulators to smem, add bias, route to destination
    __syncthreads();
#pragma unroll
    for (int i = 0; i < 2; i++)
#pragma unroll
        for (int j = 0; j < 2; j++)
            wmma::store_matrix_sync(&sm.stage[w][i * 16][j * 16], cf[i][j], 36, wmma::mem_row_major);
    __syncwarp();

    {
        int r = row0 + wy * 32 + lane;
        int cbase = col0 + wx * 32;
        bool alt = SELECT && (g_deg[r] == 0);
#pragma unroll
        for (int j = 0; j < 8; j++) {
            int cc = cbase + j * 4;
            float4 bv = *(const float4*)(bias + cc);
            float4 v;
            v.x = sm.stage[w][lane][j * 4 + 0] + bv.x;
            v.y = sm.stage[w][lane][j * 4 + 1] + bv.y;
            v.z = sm.stage[w][lane][j * 4 + 2] + bv.z;
            v.w = sm.stage[w][lane][j * 4 + 3] + bv.w;
            if (CSEL == 0) {
                if (cbase < 256) {                       // q -> fp32
                    *(float4*)(g_q + (size_t)r * DD + cc) = v;
                } else {                                 // k,v -> fp16
                    __half2 h01 = __floats2half2_rn(v.x, v.y);
                    __half2 h23 = __floats2half2_rn(v.z, v.w);
                    uint2 hv;
                    hv.x = *(unsigned*)&h01;
                    hv.y = *(unsigned*)&h23;
                    *(uint2*)((__half*)g_kvh_raw + (size_t)r * 512 + (cc - 256)) = hv;
                }
            } else {
                float* C = (CSEL == 1) ? g_x : g_y;
                if (SELECT && alt) v = *(const float4*)(emb + (size_t)r * DD + cc);
                *(float4*)(C + (size_t)r * Nc + cc) = v;
            }
        }
    }
}

// ======== sparse attention (fp16 k/v): 4-lane dot groups, 16 neighbors per warp-iter ========
// Block = node, 8 warps = 8 heads. Lane: group g = lane>>2 (neighbor slot 0..7),
// d8 = (lane&3)*8 (8-dim chunk). 2x unrolled, MLP=4. No online max (scores ~N(0,0.1));
// exp clamped at 80; exp(-inf)=0 masks the tail.
__global__ __launch_bounds__(256) void attn_kernel() {
    __shared__ int snbr[MAXD];
    __shared__ int sdeg;
    int n = blockIdx.x, tid = threadIdx.x;
    int w = tid >> 5, lane = tid & 31;
    int g = lane >> 2, d8 = (lane & 3) * 8;
    if (tid == 0) sdeg = g_deg[n];
    __syncthreads();
    int dg = sdeg;
    for (int i = tid; i < dg; i += 256)
        snbr[i] = g_nbr[(size_t)n * MAXD + i];   // already pre-scaled *512
    __syncthreads();

    const int woff = w * 32 + d8;

    if (dg == 0) {
        if (lane < 4) {
            *(float4*)&g_ctx[(size_t)n * DD + woff]     = make_float4(0.f, 0.f, 0.f, 0.f);
            *(float4*)&g_ctx[(size_t)n * DD + woff + 4] = make_float4(0.f, 0.f, 0.f, 0.f);
        }
        return;
    }

    float q8[8];
    *(float4*)&q8[0] = *(const float4*)(g_q + (size_t)n * DD + woff);
    *(float4*)&q8[4] = *(const float4*)(g_q + (size_t)n * DD + woff + 4);

    const float sc = 0.17677669529663687f;    // 1/sqrt(32)
    float s = 0.f;
    float acc[8] = {};
    const __half* kvh = (const __half*)g_kvh_raw;

    for (int i = 0; i < dg; i += 16) {
        int idx0 = i + g, idx1 = i + 8 + g;
        bool va = idx0 < dg, vb = idx1 < dg;
        const __half* pa = kvh + snbr[va ? idx0 : i] + woff;
        const __half* pb = kvh + snbr[vb ? idx1 : i] + woff;
        uint4 ka = *(const uint4*)pa;
        uint4 kb = *(const uint4*)pb;
        uint4 vaa = *(const uint4*)(pa + 256);
        uint4 vbb = *(const uint4*)(pb + 256);

        float2 a0 = __half22float2(*(__half2*)&ka.x);
        float2 a1 = __half22float2(*(__half2*)&ka.y);
        float2 a2 = __half22float2(*(__half2*)&ka.z);
        float2 a3 = __half22float2(*(__half2*)&ka.w);
        float2 b0 = __half22float2(*(__half2*)&kb.x);
        float2 b1 = __half22float2(*(__half2*)&kb.y);
        float2 b2 = __half22float2(*(__half2*)&kb.z);
        float2 b3 = __half22float2(*(__half2*)&kb.w);

        float p0 = q8[0] * a0.x + q8[1] * a0.y + q8[2] * a1.x + q8[3] * a1.y
                 + q8[4] * a2.x + q8[5] * a2.y + q8[6] * a3.x + q8[7] * a3.y;
        float p1 = q8[0] * b0.x + q8[1] * b0.y + q8[2] * b1.x + q8[3] * b1.y
                 + q8[4] * b2.x + q8[5] * b2.y + q8[6] * b3.x + q8[7] * b3.y;
        p0 += __shfl_xor_sync(0xffffffffu, p0, 1);
        p1 += __shfl_xor_sync(0xffffffffu, p1, 1);
        p0 += __shfl_xor_sync(0xffffffffu, p0, 2);
        p1 += __shfl_xor_sync(0xffffffffu, p1, 2);
        p0 = va ? fminf(p0 * sc, 80.f) : -INFINITY;
        p1 = vb ? fminf(p1 * sc, 80.f) : -INFINITY;
        float e0 = __expf(p0);
        float e1 = __expf(p1);
        s += e0 + e1;

        float2 w0 = __half22float2(*(__half2*)&vaa.x);
        float2 w1 = __half22float2(*(__half2*)&vaa.y);
        float2 w2 = __half22float2(*(__half2*)&vaa.z);
        float2 w3 = __half22float2(*(__half2*)&vaa.w);
        acc[0] += e0 * w0.x; acc[1] += e0 * w0.y;
        acc[2] += e0 * w1.x; acc[3] += e0 * w1.y;
        acc[4] += e0 * w2.x; acc[5] += e0 * w2.y;
        acc[6] += e0 * w3.x; acc[7] += e0 * w3.y;
        float2 u0 = __half22float2(*(__half2*)&vbb.x);
        float2 u1 = __half22float2(*(__half2*)&vbb.y);
        float2 u2 = __half22float2(*(__half2*)&vbb.z);
        float2 u3 = __half22float2(*(__half2*)&vbb.w);
        acc[0] += e1 * u0.x; acc[1] += e1 * u0.y;
        acc[2] += e1 * u1.x; acc[3] += e1 * u1.y;
        acc[4] += e1 * u2.x; acc[5] += e1 * u2.y;
        acc[6] += e1 * u3.x; acc[7] += e1 * u3.y;
    }

    // merge the 8 group states (lanes differing in bits 2,3,4)
#pragma unroll
    for (int o = 4; o <= 16; o <<= 1) {
        s += __shfl_xor_sync(0xffffffffu, s, o);
#pragma unroll
        for (int j = 0; j < 8; j++)
            acc[j] += __shfl_xor_sync(0xffffffffu, acc[j], o);
    }
    if (lane < 4) {
        float inv = 1.f / s;
        float4 o0 = make_float4(acc[0] * inv, acc[1] * inv, acc[2] * inv, acc[3] * inv);
        float4 o1 = make_float4(acc[4] * inv, acc[5] * inv, acc[6] * inv, acc[7] * inv);
        *(float4*)&g_ctx[(size_t)n * DD + woff]     = o0;
        *(float4*)&g_ctx[(size_t)n * DD + woff + 4] = o1;
    }
}

// -------- fused LayerNorm + exact GELU --------
__global__ void ln_gelu_kernel(const float* __restrict__ g, const float* __restrict__ beta,
                               float* __restrict__ out) {
    __shared__ float red1[8];
    __shared__ float red2[8];
    int r = blockIdx.x;
    int t = threadIdx.x;
    float v = g_y[(size_t)r * DD + t];

    float x = v, x2 = v * v;
#pragma unroll
    for (int o = 16; o; o >>= 1) {
        x  += __shfl_xor_sync(0xffffffffu, x, o);
        x2 += __shfl_xor_sync(0xffffffffu, x2, o);
    }
    if ((t & 31) == 0) { red1[t >> 5] = x; red2[t >> 5] = x2; }
    __syncthreads();
    float sum = 0.f, ss = 0.f;
#pragma unroll
    for (int i = 0; i < 8; i++) { sum += red1[i]; ss += red2[i]; }
    float mean = sum * (1.f / 256.f);
    float var  = ss * (1.f / 256.f) - mean * mean;

    float yv = (v - mean) * rsqrtf(var + 1e-5f) * g[t] + beta[t];
    out[(size_t)r * DD + t] = 0.5f * yv * (1.f + erff(yv * 0.70710678118654752f));
}

// ------------------------------------------------------------------
extern "C" void kernel_launch(void* const* d_in, const int* in_sizes, int n_in,
                              void* d_out, int out_size) {
    const float* emb   = (const float*)d_in[0];
    const int*   ei    = (const int*)d_in[1];     // int32 (JAX default)
    const float* w_in  = (const float*)d_in[2];
    const float* b_in  = (const float*)d_in[3];
    const float* w_out = (const float*)d_in[4];
    const float* b_out = (const float*)d_in[5];
    const float* w_lin = (const float*)d_in[6];
    const float* b_lin = (const float*)d_in[7];
    const float* ln_g  = (const float*)d_in[8];
    const float* ln_b  = (const float*)d_in[9];
    float* out = (float*)d_out;

    const int ne = in_sizes[1] / 2;

    // 1. adjacency (g_adj is zero at start; compact re-zeroes it for replay)
    build_adj_kernel<<<(ne + 255) / 256, 256>>>(ei, ne);
    compact_kernel<<<NN / 8, 256>>>();

    // 2. qkv = emb @ W_in^T + b_in  -> q fp32 (g_q), k/v fp16 (g_kvh)
    gemm_kernel<0, 0, false><<<dim3(768 / BN, NN / BM), GNT>>>(emb, w_in, b_in, 768);

    // 3. sparse masked attention -> ctx [4096, 256]
    attn_kernel<<<NN, 256>>>();

    // 4. x = has_nb ? ctx @ W_out^T + b_out : emb
    gemm_kernel<1, 1, true><<<dim3(DD / BN, NN / BM), GNT>>>(emb, w_out, b_out, DD);

    // 5. y = x @ W_lin^T + b_lin
    gemm_kernel<2, 2, false><<<dim3(DD / BN, NN / BM), GNT>>>(emb, w_lin, b_lin, DD);

    // 6. LayerNorm + exact GELU -> out
    ln_gelu_kernel<<<NN, 256>>>(ln_g, ln_b, out);
}

// round 12
// speedup vs baseline: 1.1691x; 1.0150x over previous
#include <cuda_runtime.h>
#include <cuda_fp16.h>
#include <mma.h>
#include <math.h>

using namespace nvcuda;

// Problem constants (fixed shapes)
#define NN 4096
#define DD 256
#define NW 128          // adjacency words per row (4096/32)
#define MAXD 512        // max neighbors kept (avg ~64 for random E=131072 graph)

// -------- static device scratch --------
__device__ unsigned g_adj[NN * NW];        // 2 MB bitmask adjacency
__device__ int      g_deg[NN];
__device__ int      g_nbr[NN * MAXD];      // 8 MB compact neighbor lists (pre-scaled *512)
__device__ float    g_q  [NN * DD];        // 4 MB  (q, fp32)
__device__ uint4    g_kvh_raw[NN * 64];    // 4 MB  (k,v as fp16: 512 halves/node)
__device__ float    g_ctx[NN * DD];        // 4 MB
__device__ float    g_x  [NN * DD];        // 4 MB
__device__ float    g_y  [NN * DD];        // 4 MB

// -------- scatter edges (symmetric, no self loops, dedup via OR); edge_index is int32 --------
__global__ void build_adj_kernel(const int* __restrict__ ei, int ne) {
    int e = blockIdx.x * blockDim.x + threadIdx.x;
    if (e >= ne) return;
    int s = ei[e];
    int d = ei[ne + e];
    if (s == d) return;
    if ((unsigned)s >= NN || (unsigned)d >= NN) return;
    atomicOr(&g_adj[s * NW + (d >> 5)], 1u << (d & 31));
    atomicOr(&g_adj[d * NW + (s >> 5)], 1u << (s & 31));
}

// -------- warp-per-row compaction (deterministic, sorted); re-zeroes g_adj for replay --------
__global__ __launch_bounds__(256) void compact_kernel() {
    int n = blockIdx.x * 8 + (threadIdx.x >> 5);
    int lane = threadIdx.x & 31;

    uint4 wv = *(uint4*)&g_adj[n * NW + lane * 4];
    *(uint4*)&g_adj[n * NW + lane * 4] = make_uint4(0u, 0u, 0u, 0u);  // reset for replay

    int c = __popc(wv.x) + __popc(wv.y) + __popc(wv.z) + __popc(wv.w);
    int x = c;
#pragma unroll
    for (int o = 1; o < 32; o <<= 1) {
        int y = __shfl_up_sync(0xffffffffu, x, o);
        if (lane >= o) x += y;
    }
    int total = __shfl_sync(0xffffffffu, x, 31);
    int base = x - c;                       // exclusive prefix

    int* dst = g_nbr + (size_t)n * MAXD;
    unsigned ws[4] = {wv.x, wv.y, wv.z, wv.w};
#pragma unroll
    for (int u = 0; u < 4; u++) {
        unsigned bits = ws[u];
        int boff = (lane * 4 + u) * 32;
        while (bits) {
            int b = __ffs(bits) - 1;
            bits &= bits - 1;
            if (base < MAXD) dst[base] = (boff + b) * 512;   // pre-scaled element offset
            base++;
        }
    }
    if (lane == 31) g_deg[n] = (total < MAXD) ? total : MAXD;
}

// ======== tf32 wmma GEMM: C[M,Nc] = A[M,K] @ B[Nc,K]^T + bias ========
// BM=64, BN=64, BK=16, 128 threads (4 warps 2x2, warp tile 32x32 = 2x2 m16n16k8),
// double-buffered smem, tf32 RN at smem store, smem-staged epilogue.
// ASEL: 0 = emb, 1 = g_ctx, 2 = g_x
// CSEL: 0 = qkv split output (q fp32 / kv fp16), 1 = g_x (+SELECT), 2 = g_y
#define BM 64
#define BN 64
#define GBK 16
#define BKP 20
#define GNT 128

struct GemmSmem {
    union {
        struct {
            float As[2][BM][BKP];   // 10240 B
            float Bs[2][BN][BKP];   // 10240 B
        } p;
        float stage[4][32][36];     // 18432 B (epilogue staging)
    };
};

template<int ASEL, int CSEL, bool SELECT>
__global__ __launch_bounds__(GNT) void gemm_kernel(const float* __restrict__ emb,
                                                   const float* __restrict__ B,
                                                   const float* __restrict__ bias,
                                                   int Nc) {
    const float* A = (ASEL == 0) ? emb : (ASEL == 1 ? (const float*)g_ctx : (const float*)g_x);
    const int K = DD;

    __shared__ GemmSmem sm;

    const int tid = threadIdx.x;
    const int w = tid >> 5, lane = tid & 31;
    const int wy = w >> 1, wx = w & 1;          // warp grid 2x2
    const int row0 = blockIdx.y * BM;
    const int col0 = blockIdx.x * BN;

    float4 ra[2], rb[2];
    auto gload = [&](int k0) {
#pragma unroll
        for (int u = 0; u < 2; u++) {
            int i = tid + u * GNT;
            int r = i >> 2, kk = (i & 3) * 4;
            ra[u] = *(const float4*)(A + (size_t)(row0 + r) * K + k0 + kk);
            rb[u] = *(const float4*)(B + (size_t)(col0 + r) * K + k0 + kk);
        }
    };
    auto sstore = [&](int buf) {
#pragma unroll
        for (int u = 0; u < 2; u++) {
            int i = tid + u * GNT;
            int r = i >> 2, kk = (i & 3) * 4;
            sm.p.As[buf][r][kk + 0] = wmma::__float_to_tf32(ra[u].x);
            sm.p.As[buf][r][kk + 1] = wmma::__float_to_tf32(ra[u].y);
            sm.p.As[buf][r][kk + 2] = wmma::__float_to_tf32(ra[u].z);
            sm.p.As[buf][r][kk + 3] = wmma::__float_to_tf32(ra[u].w);
            sm.p.Bs[buf][r][kk + 0] = wmma::__float_to_tf32(rb[u].x);
            sm.p.Bs[buf][r][kk + 1] = wmma::__float_to_tf32(rb[u].y);
            sm.p.Bs[buf][r][kk + 2] = wmma::__float_to_tf32(rb[u].z);
            sm.p.Bs[buf][r][kk + 3] = wmma::__float_to_tf32(rb[u].w);
        }
    };

    wmma::fragment<wmma::accumulator, 16, 16, 8, float> cf[2][2];
#pragma unroll
    for (int i = 0; i < 2; i++)
#pragma unroll
        for (int j = 0; j < 2; j++)
            wmma::fill_fragment(cf[i][j], 0.0f);

    gload(0);
    sstore(0);
    __syncthreads();

    const int KT = K / GBK;
    for (int kt = 0; kt < KT; kt++) {
        int buf = kt & 1;
        if (kt + 1 < KT) gload((kt + 1) * GBK);
#pragma unroll
        for (int ks = 0; ks < GBK; ks += 8) {
            wmma::fragment<wmma::matrix_a, 16, 16, 8, wmma::precision::tf32, wmma::row_major> af[2];
            wmma::fragment<wmma::matrix_b, 16, 16, 8, wmma::precision::tf32, wmma::col_major> bf[2];
#pragma unroll
            for (int i = 0; i < 2; i++)
                wmma::load_matrix_sync(af[i], &sm.p.As[buf][wy * 32 + i * 16][ks], BKP);
#pragma unroll
            for (int j = 0; j < 2; j++)
                wmma::load_matrix_sync(bf[j], &sm.p.Bs[buf][wx * 32 + j * 16][ks], BKP);
#pragma unroll
            for (int i = 0; i < 2; i++)
#pragma unroll
                for (int j = 0; j < 2; j++)
                    wmma::mma_sync(cf[i][j], af[i], bf[j], cf[i][j]);
        }
        if (kt + 1 < KT) {
            sstore(buf ^ 1);
            __syncthreads();
        }
    }

    // epilogue: stage accumulators to smem, add bias, route to destination
    __syncthreads();
#pragma unroll
    for (int i = 0; i < 2; i++)
#pragma unroll
        for (int j = 0; j < 2; j++)
            wmma::store_matrix_sync(&sm.stage[w][i * 16][j * 16], cf[i][j], 36, wmma::mem_row_major);
    __syncwarp();

    {
        int r = row0 + wy * 32 + lane;
        int cbase = col0 + wx * 32;
        bool alt = SELECT && (g_deg[r] == 0);
#pragma unroll
        for (int j = 0; j < 8; j++) {
            int cc = cbase + j * 4;
            float4 bv = *(const float4*)(bias + cc);
            float4 v;
            v.x = sm.stage[w][lane][j * 4 + 0] + bv.x;
            v.y = sm.stage[w][lane][j * 4 + 1] + bv.y;
            v.z = sm.stage[w][lane][j * 4 + 2] + bv.z;
            v.w = sm.stage[w][lane][j * 4 + 3] + bv.w;
            if (CSEL == 0) {
                if (cbase < 256) {                       // q -> fp32
                    *(float4*)(g_q + (size_t)r * DD + cc) = v;
                } else {                                 // k,v -> fp16
                    __half2 h01 = __floats2half2_rn(v.x, v.y);
                    __half2 h23 = __floats2half2_rn(v.z, v.w);
                    uint2 hv;
                    hv.x = *(unsigned*)&h01;
                    hv.y = *(unsigned*)&h23;
                    *(uint2*)((__half*)g_kvh_raw + (size_t)r * 512 + (cc - 256)) = hv;
                }
            } else {
                float* C = (CSEL == 1) ? g_x : g_y;
                if (SELECT && alt) v = *(const float4*)(emb + (size_t)r * DD + cc);
                *(float4*)(C + (size_t)r * Nc + cc) = v;
            }
        }
    }
}

// ======== sparse attention (fp16 k/v): half2 score dot, 16 neighbors per warp-iter ========
// Block = node, 8 warps = 8 heads. Lane: group g = lane>>2 (neighbor slot 0..7),
// d8 = (lane&3)*8 (8-dim chunk). Score dot in half2 (q pre-converted); v-accum fp32.
// No online max (scores ~N(0,0.1)); exp clamped at 80; exp(-inf)=0 masks the tail.
__global__ __launch_bounds__(256) void attn_kernel() {
    __shared__ int snbr[MAXD];
    __shared__ int sdeg;
    int n = blockIdx.x, tid = threadIdx.x;
    int w = tid >> 5, lane = tid & 31;
    int g = lane >> 2, d8 = (lane & 3) * 8;
    if (tid == 0) sdeg = g_deg[n];
    __syncthreads();
    int dg = sdeg;
    for (int i = tid; i < dg; i += 256)
        snbr[i] = g_nbr[(size_t)n * MAXD + i];   // already pre-scaled *512
    __syncthreads();

    const int woff = w * 32 + d8;

    if (dg == 0) {
        if (lane < 4) {
            *(float4*)&g_ctx[(size_t)n * DD + woff]     = make_float4(0.f, 0.f, 0.f, 0.f);
            *(float4*)&g_ctx[(size_t)n * DD + woff + 4] = make_float4(0.f, 0.f, 0.f, 0.f);
        }
        return;
    }

    // q: 8 dims per lane, converted to half2 once
    float4 qa = *(const float4*)(g_q + (size_t)n * DD + woff);
    float4 qb = *(const float4*)(g_q + (size_t)n * DD + woff + 4);
    __half2 qh[4];
    qh[0] = __floats2half2_rn(qa.x, qa.y);
    qh[1] = __floats2half2_rn(qa.z, qa.w);
    qh[2] = __floats2half2_rn(qb.x, qb.y);
    qh[3] = __floats2half2_rn(qb.z, qb.w);

    const float sc = 0.17677669529663687f;    // 1/sqrt(32)
    float s = 0.f;
    float acc[8] = {};
    const __half* kvh = (const __half*)g_kvh_raw;

    for (int i = 0; i < dg; i += 16) {
        int idx0 = i + g, idx1 = i + 8 + g;
        bool va = idx0 < dg, vb = idx1 < dg;
        const __half* pa = kvh + snbr[va ? idx0 : i] + woff;
        const __half* pb = kvh + snbr[vb ? idx1 : i] + woff;
        uint4 ka = *(const uint4*)pa;
        uint4 kb = *(const uint4*)pb;
        uint4 vaa = *(const uint4*)(pa + 256);
        uint4 vbb = *(const uint4*)(pb + 256);

        // half2 score dots
        const __half2* kha = (const __half2*)&ka;
        const __half2* khb = (const __half2*)&kb;
        __half2 pha = __hmul2(qh[0], kha[0]);
        __half2 phb = __hmul2(qh[0], khb[0]);
        pha = __hfma2(qh[1], kha[1], pha);
        phb = __hfma2(qh[1], khb[1], phb);
        pha = __hfma2(qh[2], kha[2], pha);
        phb = __hfma2(qh[2], khb[2], phb);
        pha = __hfma2(qh[3], kha[3], pha);
        phb = __hfma2(qh[3], khb[3], phb);
        float2 pfa = __half22float2(pha);
        float2 pfb = __half22float2(phb);
        float p0 = pfa.x + pfa.y;
        float p1 = pfb.x + pfb.y;

        p0 += __shfl_xor_sync(0xffffffffu, p0, 1);
        p1 += __shfl_xor_sync(0xffffffffu, p1, 1);
        p0 += __shfl_xor_sync(0xffffffffu, p0, 2);
        p1 += __shfl_xor_sync(0xffffffffu, p1, 2);
        p0 = va ? fminf(p0 * sc, 80.f) : -INFINITY;
        p1 = vb ? fminf(p1 * sc, 80.f) : -INFINITY;
        float e0 = __expf(p0);
        float e1 = __expf(p1);
        s += e0 + e1;

        float2 w0 = __half22float2(*(__half2*)&vaa.x);
        float2 w1 = __half22float2(*(__half2*)&vaa.y);
        float2 w2 = __half22float2(*(__half2*)&vaa.z);
        float2 w3 = __half22float2(*(__half2*)&vaa.w);
        acc[0] += e0 * w0.x; acc[1] += e0 * w0.y;
        acc[2] += e0 * w1.x; acc[3] += e0 * w1.y;
        acc[4] += e0 * w2.x; acc[5] += e0 * w2.y;
        acc[6] += e0 * w3.x; acc[7] += e0 * w3.y;
        float2 u0 = __half22float2(*(__half2*)&vbb.x);
        float2 u1 = __half22float2(*(__half2*)&vbb.y);
        float2 u2 = __half22float2(*(__half2*)&vbb.z);
        float2 u3 = __half22float2(*(__half2*)&vbb.w);
        acc[0] += e1 * u0.x; acc[1] += e1 * u0.y;
        acc[2] += e1 * u1.x; acc[3] += e1 * u1.y;
        acc[4] += e1 * u2.x; acc[5] += e1 * u2.y;
        acc[6] += e1 * u3.x; acc[7] += e1 * u3.y;
    }

    // merge the 8 group states (lanes differing in bits 2,3,4)
#pragma unroll
    for (int o = 4; o <= 16; o <<= 1) {
        s += __shfl_xor_sync(0xffffffffu, s, o);
#pragma unroll
        for (int j = 0; j < 8; j++)
            acc[j] += __shfl_xor_sync(0xffffffffu, acc[j], o);
    }
    if (lane < 4) {
        float inv = 1.f / s;
        float4 o0 = make_float4(acc[0] * inv, acc[1] * inv, acc[2] * inv, acc[3] * inv);
        float4 o1 = make_float4(acc[4] * inv, acc[5] * inv, acc[6] * inv, acc[7] * inv);
        *(float4*)&g_ctx[(size_t)n * DD + woff]     = o0;
        *(float4*)&g_ctx[(size_t)n * DD + woff + 4] = o1;
    }
}

// -------- warp-per-row LayerNorm + exact GELU (8 rows/block, no shared mem) --------
__global__ __launch_bounds__(256) void ln_gelu_kernel(const float* __restrict__ g,
                                                      const float* __restrict__ beta,
                                                      float* __restrict__ out) {
    int r = blockIdx.x * 8 + (threadIdx.x >> 5);
    int lane = threadIdx.x & 31;
    const float* row = g_y + (size_t)r * DD + lane * 8;
    float4 v0 = *(const float4*)row;
    float4 v1 = *(const float4*)(row + 4);

    float sum = v0.x + v0.y + v0.z + v0.w + v1.x + v1.y + v1.z + v1.w;
    float ss  = v0.x * v0.x + v0.y * v0.y + v0.z * v0.z + v0.w * v0.w
              + v1.x * v1.x + v1.y * v1.y + v1.z * v1.z + v1.w * v1.w;
#pragma unroll
    for (int o = 16; o; o >>= 1) {
        sum += __shfl_xor_sync(0xffffffffu, sum, o);
        ss  += __shfl_xor_sync(0xffffffffu, ss, o);
    }
    float mean = sum * (1.f / 256.f);
    float var  = ss * (1.f / 256.f) - mean * mean;
    float rstd = rsqrtf(var + 1e-5f);

    float4 g0 = *(const float4*)(g + lane * 8);
    float4 g1 = *(const float4*)(g + lane * 8 + 4);
    float4 b0 = *(const float4*)(beta + lane * 8);
    float4 b1 = *(const float4*)(beta + lane * 8 + 4);

    float vv[8] = {v0.x, v0.y, v0.z, v0.w, v1.x, v1.y, v1.z, v1.w};
    float gg[8] = {g0.x, g0.y, g0.z, g0.w, g1.x, g1.y, g1.z, g1.w};
    float bb[8] = {b0.x, b0.y, b0.z, b0.w, b1.x, b1.y, b1.z, b1.w};
    float oo[8];
#pragma unroll
    for (int j = 0; j < 8; j++) {
        float yv = (vv[j] - mean) * rstd * gg[j] + bb[j];
        oo[j] = 0.5f * yv * (1.f + erff(yv * 0.70710678118654752f));
    }
    float* orow = out + (size_t)r * DD + lane * 8;
    *(float4*)orow       = make_float4(oo[0], oo[1], oo[2], oo[3]);
    *(float4*)(orow + 4) = make_float4(oo[4], oo[5], oo[6], oo[7]);
}

// ------------------------------------------------------------------
extern "C" void kernel_launch(void* const* d_in, const int* in_sizes, int n_in,
                              void* d_out, int out_size) {
    const float* emb   = (const float*)d_in[0];
    const int*   ei    = (const int*)d_in[1];     // int32 (JAX default)
    const float* w_in  = (const float*)d_in[2];
    const float* b_in  = (const float*)d_in[3];
    const float* w_out = (const float*)d_in[4];
    const float* b_out = (const float*)d_in[5];
    const float* w_lin = (const float*)d_in[6];
    const float* b_lin = (const float*)d_in[7];
    const float* ln_g  = (const float*)d_in[8];
    const float* ln_b  = (const float*)d_in[9];
    float* out = (float*)d_out;

    const int ne = in_sizes[1] / 2;

    // 1. adjacency (g_adj is zero at start; compact re-zeroes it for replay)
    build_adj_kernel<<<(ne + 255) / 256, 256>>>(ei, ne);
    compact_kernel<<<NN / 8, 256>>>();

    // 2. qkv = emb @ W_in^T + b_in  -> q fp32 (g_q), k/v fp16 (g_kvh)
    gemm_kernel<0, 0, false><<<dim3(768 / BN, NN / BM), GNT>>>(emb, w_in, b_in, 768);

    // 3. sparse masked attention -> ctx [4096, 256]
    attn_kernel<<<NN, 256>>>();

    // 4. x = has_nb ? ctx @ W_out^T + b_out : emb
    gemm_kernel<1, 1, true><<<dim3(DD / BN, NN / BM), GNT>>>(emb, w_out, b_out, DD);

    // 5. y = x @ W_lin^T + b_lin
    gemm_kernel<2, 2, false><<<dim3(DD / BN, NN / BM), GNT>>>(emb, w_lin, b_lin, DD);

    // 6. LayerNorm + exact GELU -> out
    ln_gelu_kernel<<<NN / 8, 256>>>(ln_g, ln_b, out);
}